// round 12
// baseline (speedup 1.0000x reference)
#include <cuda_runtime.h>
#include <cuda_bf16.h>
#include <math.h>

// feat_rgb: [B=4, C=256, IH=128, IW=512] fp32
// out:      [4, 256, BEV_H=128, BEV_W=512] fp32
#define BEV_H 128
#define BEV_W 512
#define IH    128
#define IW    512
#define NB    4
#define NC    256
#define PLANE (IH * IW)
#define OPLANE (BEV_H * BEV_W)
#define NPIX  (NB * BEV_H * BEV_W)     // 262144
#define CHUNK 32                       // channels per thread (fully unrolled)
#define NCH   (NC / CHUNK)             // 8

#define TWO_PI_F   6.2831853071795864769f
#define PI_F       3.1415926535897932385f
#define HALF_PI_F  1.5707963267948966192f

// Precomputed per-(b,pixel) sampling records (8.4 MB total, L2-resident)
__device__ int4   g_idx[NPIX];   // i00, i01, i10, i11
__device__ float4 g_w[NPIX];     // w_nw, w_ne, w_sw, w_se

__device__ __forceinline__ float mod2pi(float x) {
    float m = fmodf(x, TWO_PI_F);
    if (m < 0.0f) m += TWO_PI_F;
    return m;
}

// ---------------- Kernel A: coordinates -> records (once per pixel) --------
__global__ void __launch_bounds__(256)
bev_coords_kernel(const float* __restrict__ rot,
                  const float* __restrict__ shift_u,
                  const float* __restrict__ shift_v,
                  const float* __restrict__ mpp)
{
    int t = blockIdx.x * blockDim.x + threadIdx.x;   // [b][i][j], j fastest
    int j = t & (BEV_W - 1);
    int i = (t >> 9) & (BEV_H - 1);
    int b = t >> 16;

    const float r  = rot[b];
    const float su = shift_u[b];
    const float sv = shift_v[b];
    const float m  = mpp[0];

    float center_v = (float)BEV_H * 0.5f - 0.5f + sv;
    float center_u = (float)BEV_W * 0.5f - 0.5f + su;
    float dy = (float)i - center_v;
    float dx = (float)j - center_u;
    float radius = sqrtf(dy * dy + dx * dx);

    float theta = atan2f(dy, dx);
    theta = mod2pi(-HALF_PI_F + mod2pi(theta));
    theta = mod2pi(theta + r * TWO_PI_F);
    float u = theta / TWO_PI_F * (float)IW;

    float dist = radius * m;
    float phi  = atan2f(dist, -2.0f);
    float v    = phi / PI_F * (float)IH;

    float fx = floorf(u);
    float fy = floorf(v);
    float x0 = fminf(fmaxf(fx,        0.0f), (float)(IW - 1));
    float x1 = fminf(fmaxf(fx + 1.0f, 0.0f), (float)(IW - 1));
    float y0 = fminf(fmaxf(fy,        0.0f), (float)(IH - 1));
    float y1 = fminf(fmaxf(fy + 1.0f, 0.0f), (float)(IH - 1));

    float4 w;
    w.x = (x1 - u) * (y1 - v);   // w_nw
    w.y = (u - x0) * (y1 - v);   // w_ne
    w.z = (x1 - u) * (v - y0);   // w_sw
    w.w = (u - x0) * (v - y0);   // w_se

    int ix0 = (int)x0, ix1 = (int)x1, iy0 = (int)y0, iy1 = (int)y1;
    int4 idx;
    idx.x = iy0 * IW + ix0;
    idx.y = iy0 * IW + ix1;
    idx.z = iy1 * IW + ix0;
    idx.w = iy1 * IW + ix1;

    g_idx[t] = idx;
    g_w[t]   = w;
}

// ---------------- Kernel B: gather + blend, full unroll w/ imm offsets -----
// launch_bounds(256,3): ~84 regs/thread -> deeper LDG front-batching.
__global__ void __launch_bounds__(256, 3)
bev_sample_kernel(const float* __restrict__ feat,
                  float* __restrict__ out)
{
    int t = blockIdx.x * blockDim.x + threadIdx.x;
    // layout: [b][cc][i][j], j fastest -> warp = 32 consecutive j (critical)
    int j  = t & (BEV_W - 1);
    int i  = (t >> 9) & (BEV_H - 1);
    int cc = (t >> 16) & (NCH - 1);
    int b  = t >> 19;

    int rec = (b << 16) | (i << 9) | j;          // record index (channel-free)
    const int4   idx = g_idx[rec];
    const float4 w   = g_w[rec];

    int c0 = cc * CHUNK;
    // Four corner base pointers: all subsequent accesses use compile-time
    // immediate offsets (c*PLANE*4 <= 8,126,464 B < 2^23 -> LDG [R+imm]).
    const float* __restrict__ p  = feat + (size_t)(b * NC + c0) * PLANE;
    const float* __restrict__ pa = p + idx.x;
    const float* __restrict__ pb = p + idx.y;
    const float* __restrict__ pc = p + idx.z;
    const float* __restrict__ pd = p + idx.w;
    float* __restrict__ o = out + (size_t)((b * NC + c0) * BEV_H + i) * BEV_W + j;

    #pragma unroll
    for (int c = 0; c < CHUNK; ++c) {
        float a00 = __ldg(pa + c * PLANE);
        float a01 = __ldg(pb + c * PLANE);
        float a10 = __ldg(pc + c * PLANE);
        float a11 = __ldg(pd + c * PLANE);
        o[c * OPLANE] = a00 * w.x + a01 * w.y + a10 * w.z + a11 * w.w;
    }
}

extern "C" void kernel_launch(void* const* d_in, const int* in_sizes, int n_in,
                              void* d_out, int out_size)
{
    const float* feat    = (const float*)d_in[0];
    const float* rot     = (const float*)d_in[1];
    const float* shift_u = (const float*)d_in[2];
    const float* shift_v = (const float*)d_in[3];
    const float* mpp     = (const float*)d_in[4];
    float* out = (float*)d_out;

    // Kernel A: one thread per (b, pixel)
    bev_coords_kernel<<<NPIX / 256, 256>>>(rot, shift_u, shift_v, mpp);

    // Kernel B: one thread per (b, channel-chunk, pixel)
    int total = NB * NCH * BEV_H * BEV_W;   // 2,097,152
    bev_sample_kernel<<<total / 256, 256>>>(feat, out);
}

// round 13
// speedup vs baseline: 1.0333x; 1.0333x over previous
#include <cuda_runtime.h>
#include <cuda_bf16.h>
#include <math.h>

// feat_rgb: [B=4, C=256, IH=128, IW=512] fp32
// out:      [4, 256, BEV_H=128, BEV_W=512] fp32
#define BEV_H 128
#define BEV_W 512
#define IH    128
#define IW    512
#define NB    4
#define NC    256
#define PLANE (IH * IW)
#define OPLANE (BEV_H * BEV_W)
#define NPIX  (NB * BEV_H * BEV_W)     // 262144
#define CHUNK 16                       // channels per thread (fully unrolled)
#define NCH   (NC / CHUNK)             // 16

#define TWO_PI_F   6.2831853071795864769f
#define PI_F       3.1415926535897932385f
#define HALF_PI_F  1.5707963267948966192f

// Precomputed per-(b,pixel) sampling records (8.4 MB total, L2-resident)
__device__ int4   g_idx[NPIX];   // i00, i01, i10, i11
__device__ float4 g_w[NPIX];     // w_nw, w_ne, w_sw, w_se

__device__ __forceinline__ float mod2pi(float x) {
    float m = fmodf(x, TWO_PI_F);
    if (m < 0.0f) m += TWO_PI_F;
    return m;
}

// ---------------- Kernel A: coordinates -> records (once per pixel) --------
__global__ void __launch_bounds__(256)
bev_coords_kernel(const float* __restrict__ rot,
                  const float* __restrict__ shift_u,
                  const float* __restrict__ shift_v,
                  const float* __restrict__ mpp)
{
    int t = blockIdx.x * blockDim.x + threadIdx.x;   // [b][i][j], j fastest
    int j = t & (BEV_W - 1);
    int i = (t >> 9) & (BEV_H - 1);
    int b = t >> 16;

    const float r  = rot[b];
    const float su = shift_u[b];
    const float sv = shift_v[b];
    const float m  = mpp[0];

    float center_v = (float)BEV_H * 0.5f - 0.5f + sv;
    float center_u = (float)BEV_W * 0.5f - 0.5f + su;
    float dy = (float)i - center_v;
    float dx = (float)j - center_u;
    float radius = sqrtf(dy * dy + dx * dx);

    float theta = atan2f(dy, dx);
    theta = mod2pi(-HALF_PI_F + mod2pi(theta));
    theta = mod2pi(theta + r * TWO_PI_F);
    float u = theta / TWO_PI_F * (float)IW;

    float dist = radius * m;
    float phi  = atan2f(dist, -2.0f);
    float v    = phi / PI_F * (float)IH;

    float fx = floorf(u);
    float fy = floorf(v);
    float x0 = fminf(fmaxf(fx,        0.0f), (float)(IW - 1));
    float x1 = fminf(fmaxf(fx + 1.0f, 0.0f), (float)(IW - 1));
    float y0 = fminf(fmaxf(fy,        0.0f), (float)(IH - 1));
    float y1 = fminf(fmaxf(fy + 1.0f, 0.0f), (float)(IH - 1));

    float4 w;
    w.x = (x1 - u) * (y1 - v);   // w_nw
    w.y = (u - x0) * (y1 - v);   // w_ne
    w.z = (x1 - u) * (v - y0);   // w_sw
    w.w = (u - x0) * (v - y0);   // w_se

    int ix0 = (int)x0, ix1 = (int)x1, iy0 = (int)y0, iy1 = (int)y1;
    int4 idx;
    idx.x = iy0 * IW + ix0;
    idx.y = iy0 * IW + ix1;
    idx.z = iy1 * IW + ix0;
    idx.w = iy1 * IW + ix1;

    g_idx[t] = idx;
    g_w[t]   = w;
}

// ---------------- Kernel B: gather + blend, full unroll w/ imm offsets -----
// launch_bounds(256,5): reg cap 51 -> 40 warps/SM theoretical, batch ~6 deep.
__global__ void __launch_bounds__(256, 5)
bev_sample_kernel(const float* __restrict__ feat,
                  float* __restrict__ out)
{
    int t = blockIdx.x * blockDim.x + threadIdx.x;
    // layout: [b][cc][i][j], j fastest -> warp = 32 consecutive j (critical)
    int j  = t & (BEV_W - 1);
    int i  = (t >> 9) & (BEV_H - 1);
    int cc = (t >> 16) & (NCH - 1);
    int b  = t >> 20;

    int rec = (b << 16) | (i << 9) | j;          // record index (channel-free)
    const int4   idx = g_idx[rec];
    const float4 w   = g_w[rec];

    int c0 = cc * CHUNK;
    // Four corner base pointers: all subsequent accesses use compile-time
    // immediate offsets (c*PLANE*4 <= 3,932,160 B < 2^23 -> LDG [R+imm]).
    const float* __restrict__ p  = feat + (size_t)(b * NC + c0) * PLANE;
    const float* __restrict__ pa = p + idx.x;
    const float* __restrict__ pb = p + idx.y;
    const float* __restrict__ pc = p + idx.z;
    const float* __restrict__ pd = p + idx.w;
    float* __restrict__ o = out + (size_t)((b * NC + c0) * BEV_H + i) * BEV_W + j;

    #pragma unroll
    for (int c = 0; c < CHUNK; ++c) {
        float a00 = __ldg(pa + c * PLANE);
        float a01 = __ldg(pb + c * PLANE);
        float a10 = __ldg(pc + c * PLANE);
        float a11 = __ldg(pd + c * PLANE);
        o[c * OPLANE] = a00 * w.x + a01 * w.y + a10 * w.z + a11 * w.w;
    }
}

extern "C" void kernel_launch(void* const* d_in, const int* in_sizes, int n_in,
                              void* d_out, int out_size)
{
    const float* feat    = (const float*)d_in[0];
    const float* rot     = (const float*)d_in[1];
    const float* shift_u = (const float*)d_in[2];
    const float* shift_v = (const float*)d_in[3];
    const float* mpp     = (const float*)d_in[4];
    float* out = (float*)d_out;

    // Kernel A: one thread per (b, pixel)
    bev_coords_kernel<<<NPIX / 256, 256>>>(rot, shift_u, shift_v, mpp);

    // Kernel B: one thread per (b, channel-chunk, pixel)
    int total = NB * NCH * BEV_H * BEV_W;   // 4,194,304
    bev_sample_kernel<<<total / 256, 256>>>(feat, out);
}